// round 2
// baseline (speedup 1.0000x reference)
#include <cuda_runtime.h>

#define BB 4096
#define LL 200
#define DD 64
#define NPAIR 100   // L/2 item pairs

// Precomputed fused projection matrix: M = W_item^T @ W_target  [D, D]
__device__ float g_M[DD * DD];

// M[d][dp] = sum_e W_item[e][d] * W_target[e][dp]
__global__ void precompute_M_kernel(const float* __restrict__ W_target,
                                    const float* __restrict__ W_item) {
    int d  = blockIdx.x;    // 0..63
    int dp = threadIdx.x;   // 0..63
    float s = 0.f;
    #pragma unroll
    for (int e = 0; e < DD; ++e)
        s += W_item[e * DD + d] * W_target[e * DD + dp];
    g_M[d * DD + dp] = s;
}

__global__ __launch_bounds__(256, 6) void target_attn_kernel(
    const float* __restrict__ tk,    // [B, D]  target_key
    const float* __restrict__ ik,    // [B, L, D] item_keys
    const float* __restrict__ iv,    // [B, L, D] item_values
    const int*   __restrict__ mask,  // [B, L]
    const float* __restrict__ Wv,    // [D, D]  W_value
    float* __restrict__ out)         // [B, D]
{
    const int b    = blockIdx.x;
    const int tid  = threadIdx.x;
    const int warp = tid >> 5;
    const int lane = tid & 31;
    const int half = lane >> 4;      // 0 or 1: which item of the pair
    const int hl   = lane & 15;      // lane within half-warp

    __shared__ float s_vec[DD];          // tk, later vbar
    __shared__ float s_qk[DD];           // fused query (pre-scaled)
    __shared__ float s_w[LL];            // scores -> exp weights
    __shared__ int   s_mask[LL];
    __shared__ float s_red[8];
    __shared__ float s_vpart[16][DD];    // per-half-warp vbar partials

    // ---- coalesced mask preload + tk load ----
    if (tid < LL) s_mask[tid] = mask[b * LL + tid];
    if (tid < DD) s_vec[tid] = tk[b * DD + tid];
    __syncthreads();

    // ---- qk = (M @ tk) * (1/sqrt(D)) ----
    if (tid < DD) {
        float s = 0.f;
        #pragma unroll
        for (int j = 0; j < DD; ++j) s += g_M[tid * DD + j] * s_vec[j];
        s_qk[tid] = s * 0.125f;   // 1/sqrt(64)
    }
    __syncthreads();

    // ---- scores: warp handles an item PAIR per iter (LDG.128, half-warp reduce) ----
    const float4 q4 = reinterpret_cast<const float4*>(s_qk)[hl];
    const float4* ik4 = reinterpret_cast<const float4*>(ik + (size_t)b * LL * DD);
    for (int p = warp; p < NPAIR; p += 8) {
        float4 a = ik4[p * 32 + lane];          // 512B = items 2p, 2p+1
        float s = a.x * q4.x + a.y * q4.y + a.z * q4.z + a.w * q4.w;
        // reduce within each 16-lane half (lanes 0 and 16 end with the sums)
        s += __shfl_down_sync(0xffffffffu, s, 8);
        s += __shfl_down_sync(0xffffffffu, s, 4);
        s += __shfl_down_sync(0xffffffffu, s, 2);
        s += __shfl_down_sync(0xffffffffu, s, 1);
        if (hl == 0) {
            int l = 2 * p + half;
            s_w[l] = s_mask[l] ? s : (s - 1e8f);
        }
    }
    __syncthreads();

    // ---- softmax over L=200 ----
    float mx = -3.0e38f;
    for (int l = tid; l < LL; l += 256) mx = fmaxf(mx, s_w[l]);
    #pragma unroll
    for (int o = 16; o; o >>= 1) mx = fmaxf(mx, __shfl_down_sync(0xffffffffu, mx, o));
    if (lane == 0) s_red[warp] = mx;
    __syncthreads();
    if (tid == 0) {
        float m2 = s_red[0];
        #pragma unroll
        for (int i = 1; i < 8; ++i) m2 = fmaxf(m2, s_red[i]);
        s_red[0] = m2;
    }
    __syncthreads();
    mx = s_red[0];
    __syncthreads();

    float sum = 0.f;
    for (int l = tid; l < LL; l += 256) {
        float e = __expf(s_w[l] - mx);
        s_w[l] = e;
        sum += e;
    }
    #pragma unroll
    for (int o = 16; o; o >>= 1) sum += __shfl_down_sync(0xffffffffu, sum, o);
    if (lane == 0) s_red[warp] = sum;
    __syncthreads();
    if (tid == 0) {
        float t = 0.f;
        #pragma unroll
        for (int i = 0; i < 8; ++i) t += s_red[i];
        s_red[0] = 1.f / t;
    }
    __syncthreads();
    const float inv = s_red[0];

    // ---- vbar: pair per warp-iter, LDG.128, per-half accumulators ----
    const float4* iv4 = reinterpret_cast<const float4*>(iv + (size_t)b * LL * DD);
    float4 acc = make_float4(0.f, 0.f, 0.f, 0.f);
    for (int p = warp; p < NPAIR; p += 8) {
        float4 v = iv4[p * 32 + lane];
        float wl = s_w[2 * p + half];
        acc.x += wl * v.x;
        acc.y += wl * v.y;
        acc.z += wl * v.z;
        acc.w += wl * v.w;
    }
    reinterpret_cast<float4*>(&s_vpart[warp * 2 + half][hl * 4])[0] = acc;
    __syncthreads();

    if (tid < DD) {
        float vb = 0.f;
        #pragma unroll
        for (int p = 0; p < 16; ++p) vb += s_vpart[p][tid];
        s_vec[tid] = vb * inv;            // normalized vbar
    }
    __syncthreads();

    // ---- out = W_value @ vbar ----
    if (tid < DD) {
        float s = 0.f;
        #pragma unroll
        for (int j = 0; j < DD; ++j) s += Wv[tid * DD + j] * s_vec[j];
        out[b * DD + tid] = s;
    }
}

extern "C" void kernel_launch(void* const* d_in, const int* in_sizes, int n_in,
                              void* d_out, int out_size) {
    const float* target_key  = (const float*)d_in[0];
    const float* item_keys   = (const float*)d_in[1];
    const float* item_values = (const float*)d_in[2];
    const int*   mask        = (const int*)  d_in[3];
    const float* W_target    = (const float*)d_in[4];
    const float* W_item      = (const float*)d_in[5];
    const float* W_value     = (const float*)d_in[6];
    float* out = (float*)d_out;

    precompute_M_kernel<<<DD, DD>>>(W_target, W_item);
    target_attn_kernel<<<BB, 256>>>(target_key, item_keys, item_values,
                                    mask, W_value, out);
}

// round 4
// speedup vs baseline: 1.1693x; 1.1693x over previous
#include <cuda_runtime.h>

#define BB 4096
#define LL 200
#define DD 64
#define NPAIR 100   // L/2 item pairs

// Precomputed fused projection matrix: M = W_item^T @ W_target  [D, D]
__device__ float g_M[DD * DD];

// M[d][dp] = sum_e W_item[e][d] * W_target[e][dp]
__global__ void precompute_M_kernel(const float* __restrict__ W_target,
                                    const float* __restrict__ W_item) {
    int d  = blockIdx.x;
    int dp = threadIdx.x;
    float s = 0.f;
    #pragma unroll
    for (int e = 0; e < DD; ++e)
        s += W_item[e * DD + d] * W_target[e * DD + dp];
    g_M[d * DD + dp] = s;
}

__global__ __launch_bounds__(256, 5) void target_attn_kernel(
    const float* __restrict__ tk,    // [B, D]
    const float* __restrict__ ik,    // [B, L, D]
    const float* __restrict__ iv,    // [B, L, D]
    const int*   __restrict__ mask,  // [B, L]
    const float* __restrict__ Wv,    // [D, D]
    float* __restrict__ out)         // [B, D]
{
    const int b    = blockIdx.x;
    const int tid  = threadIdx.x;
    const int warp = tid >> 5;
    const int lane = tid & 31;
    const int half = lane >> 4;       // which item of the pair
    const int hl   = lane & 15;       // lane within half-warp
    const int st   = warp * 2 + half; // online-softmax state id (0..15)

    __shared__ __align__(16) float s_vec[DD];       // tk, later vbar
    __shared__ __align__(16) float s_qk[DD];        // fused query (pre-scaled)
    __shared__ __align__(16) float s_vpart[16][DD]; // per-state vbar partials
    __shared__ int   s_mask[LL];
    __shared__ float s_mx[16];
    __shared__ float s_sum[16];
    __shared__ float s_f[16];
    __shared__ float s_red[2];

    // ---- coalesced preloads ----
    if (tid < LL) s_mask[tid] = mask[b * LL + tid];
    if (tid < DD) s_vec[tid] = tk[b * DD + tid];
    __syncthreads();

    // ---- qk = (M @ tk) * (1/sqrt(D)) ----
    if (tid < DD) {
        float s = 0.f;
        #pragma unroll
        for (int j = 0; j < DD; ++j) s += g_M[tid * DD + j] * s_vec[j];
        s_qk[tid] = s * 0.125f;
    }
    __syncthreads();

    // ---- fused streaming pass: score + online softmax + weighted V accum ----
    const float4 q4 = reinterpret_cast<const float4*>(s_qk)[hl];
    const float4* ik4 = reinterpret_cast<const float4*>(ik + (size_t)b * LL * DD);
    const float4* iv4 = reinterpret_cast<const float4*>(iv + (size_t)b * LL * DD);

    float mx  = -3.0e38f;
    float sum = 0.f;
    float4 acc = make_float4(0.f, 0.f, 0.f, 0.f);

    // 1-deep software pipeline: ~4 LDG.128 in flight per warp
    int p = warp;                              // p < 100 always for warp < 8
    float4 a0 = ik4[p * 32 + lane];
    float4 v0 = iv4[p * 32 + lane];

    while (true) {
        const int pn = p + 8;
        float4 a1, v1;
        if (pn < NPAIR) {
            a1 = ik4[pn * 32 + lane];
            v1 = iv4[pn * 32 + lane];
        }

        // score for this half's item
        float s = a0.x * q4.x + a0.y * q4.y + a0.z * q4.z + a0.w * q4.w;
        s += __shfl_xor_sync(0xffffffffu, s, 8);
        s += __shfl_xor_sync(0xffffffffu, s, 4);
        s += __shfl_xor_sync(0xffffffffu, s, 2);
        s += __shfl_xor_sync(0xffffffffu, s, 1);
        const int l = 2 * p + half;
        if (!s_mask[l]) s -= 1e8f;

        // online softmax update
        const float nmx = fmaxf(mx, s);
        const float f   = __expf(mx - nmx);   // rescale old state
        const float w   = __expf(s  - nmx);   // weight of new item
        mx  = nmx;
        sum = sum * f + w;
        acc.x = acc.x * f + w * v0.x;
        acc.y = acc.y * f + w * v0.y;
        acc.z = acc.z * f + w * v0.z;
        acc.w = acc.w * f + w * v0.w;

        if (pn >= NPAIR) break;
        a0 = a1; v0 = v1; p = pn;
    }

    // ---- publish per-state results ----
    if (hl == 0) { s_mx[st] = mx; s_sum[st] = sum; }
    reinterpret_cast<float4*>(&s_vpart[st][hl * 4])[0] = acc;
    __syncthreads();

    // ---- merge 16 online-softmax states (warp 0) ----
    if (warp == 0) {
        float m = (lane < 16) ? s_mx[lane] : -3.0e38f;
        float gm = m;
        #pragma unroll
        for (int o = 8; o; o >>= 1) gm = fmaxf(gm, __shfl_xor_sync(0xffffffffu, gm, o));
        float fct = (lane < 16) ? __expf(m - gm) : 0.f;
        float ssc = (lane < 16) ? s_sum[lane] * fct : 0.f;
        #pragma unroll
        for (int o = 8; o; o >>= 1) ssc += __shfl_xor_sync(0xffffffffu, ssc, o);
        if (lane < 16) s_f[lane] = fct;
        if (lane == 0) s_red[0] = 1.f / ssc;
    }
    __syncthreads();
    const float inv = s_red[0];

    if (tid < DD) {
        float vb = 0.f;
        #pragma unroll
        for (int pI = 0; pI < 16; ++pI) vb += s_vpart[pI][tid] * s_f[pI];
        s_vec[tid] = vb * inv;
    }
    __syncthreads();

    // ---- out = W_value @ vbar ----
    if (tid < DD) {
        float s = 0.f;
        #pragma unroll
        for (int j = 0; j < DD; ++j) s += Wv[tid * DD + j] * s_vec[j];
        out[b * DD + tid] = s;
    }
}

extern "C" void kernel_launch(void* const* d_in, const int* in_sizes, int n_in,
                              void* d_out, int out_size) {
    const float* target_key  = (const float*)d_in[0];
    const float* item_keys   = (const float*)d_in[1];
    const float* item_values = (const float*)d_in[2];
    const int*   mask        = (const int*)  d_in[3];
    const float* W_target    = (const float*)d_in[4];
    const float* W_item      = (const float*)d_in[5];
    const float* W_value     = (const float*)d_in[6];
    float* out = (float*)d_out;

    precompute_M_kernel<<<DD, DD>>>(W_target, W_item);
    target_attn_kernel<<<BB, 256>>>(target_key, item_keys, item_values,
                                    mask, W_value, out);
}

// round 5
// speedup vs baseline: 1.2472x; 1.0666x over previous
#include <cuda_runtime.h>

#define BB 4096
#define LL 200
#define DD 64
#define NPAIR 100   // L/2 item pairs
#define NITER 13    // ceil(100/8)

// Precomputed fused projection matrix: M = W_item^T @ W_target  [D, D]
__device__ float g_M[DD * DD];

// M[d][dp] = sum_e W_item[e][d] * W_target[e][dp]
__global__ void precompute_M_kernel(const float* __restrict__ W_target,
                                    const float* __restrict__ W_item) {
    int d  = blockIdx.x;
    int dp = threadIdx.x;
    float s = 0.f;
    #pragma unroll
    for (int e = 0; e < DD; ++e)
        s += W_item[e * DD + d] * W_target[e * DD + dp];
    g_M[d * DD + dp] = s;
}

__global__ __launch_bounds__(256, 4) void target_attn_kernel(
    const float* __restrict__ tk,    // [B, D]
    const float* __restrict__ ik,    // [B, L, D]
    const float* __restrict__ iv,    // [B, L, D]
    const int*   __restrict__ mask,  // [B, L]
    const float* __restrict__ Wv,    // [D, D]
    float* __restrict__ out)         // [B, D]
{
    const int b    = blockIdx.x;
    const int tid  = threadIdx.x;
    const int warp = tid >> 5;
    const int lane = tid & 31;
    const int half = lane >> 4;       // which item of the pair
    const int hl   = lane & 15;       // lane within half-warp
    const int st   = warp * 2 + half; // online-softmax state id (0..15)

    __shared__ __align__(16) float s_vec[DD];       // tk, later vbar
    __shared__ __align__(16) float s_qk[DD];        // fused query (pre-scaled)
    __shared__ __align__(16) float s_vpart[16][DD]; // per-state vbar partials
    __shared__ float s_bias[LL];                    // 0 or -1e8 per item
    __shared__ float s_mx[16];
    __shared__ float s_sum[16];
    __shared__ float s_f[16];
    __shared__ float s_red[2];

    // ---- coalesced preloads ----
    if (tid < LL) s_bias[tid] = mask[b * LL + tid] ? 0.f : -1e8f;
    if (tid < DD) s_vec[tid] = tk[b * DD + tid];
    __syncthreads();

    // ---- qk = (M @ tk) * (1/sqrt(D)) ----
    if (tid < DD) {
        float s = 0.f;
        #pragma unroll
        for (int j = 0; j < DD; ++j) s += g_M[tid * DD + j] * s_vec[j];
        s_qk[tid] = s * 0.125f;
    }
    __syncthreads();

    // ---- fused streaming pass: 3-stage pipeline, 6 LDG.128 in flight/warp ----
    const float4 q4 = reinterpret_cast<const float4*>(s_qk)[hl];
    const float4* ik4 = reinterpret_cast<const float4*>(ik + (size_t)b * LL * DD);
    const float4* iv4 = reinterpret_cast<const float4*>(iv + (size_t)b * LL * DD);

    float mx  = -3.0e38f;
    float sum = 0.f;
    float4 acc = make_float4(0.f, 0.f, 0.f, 0.f);

    float4 A[3], V[3];
    {   // stages 0 and 1 always valid: warp+8 <= 15 < 100
        const int i0 = warp * 32 + lane;
        A[0] = ik4[i0];            V[0] = iv4[i0];
        const int i1 = i0 + 8 * 32;
        A[1] = ik4[i1];            V[1] = iv4[i1];
    }

    #pragma unroll
    for (int i = 0; i < NITER; ++i) {
        const int p  = warp + 8 * i;
        const int pf = warp + 8 * (i + 2);
        if (pf < NPAIR) {
            A[(i + 2) % 3] = ik4[pf * 32 + lane];
            V[(i + 2) % 3] = iv4[pf * 32 + lane];
        }
        if (p < NPAIR) {
            const float4 a = A[i % 3];
            const float4 v = V[i % 3];

            float s = a.x * q4.x + a.y * q4.y + a.z * q4.z + a.w * q4.w;
            s += __shfl_xor_sync(0xffffffffu, s, 8);
            s += __shfl_xor_sync(0xffffffffu, s, 4);
            s += __shfl_xor_sync(0xffffffffu, s, 2);
            s += __shfl_xor_sync(0xffffffffu, s, 1);
            s += s_bias[2 * p + half];

            const float nmx = fmaxf(mx, s);
            const float f   = __expf(mx - nmx);
            const float w   = __expf(s  - nmx);
            mx  = nmx;
            sum = sum * f + w;
            acc.x = acc.x * f + w * v.x;
            acc.y = acc.y * f + w * v.y;
            acc.z = acc.z * f + w * v.z;
            acc.w = acc.w * f + w * v.w;
        }
    }

    // ---- publish per-state results ----
    if (hl == 0) { s_mx[st] = mx; s_sum[st] = sum; }
    reinterpret_cast<float4*>(&s_vpart[st][hl * 4])[0] = acc;
    __syncthreads();

    // ---- merge 16 online-softmax states (warp 0) ----
    if (warp == 0) {
        float m = (lane < 16) ? s_mx[lane] : -3.0e38f;
        float gm = m;
        #pragma unroll
        for (int o = 8; o; o >>= 1) gm = fmaxf(gm, __shfl_xor_sync(0xffffffffu, gm, o));
        float fct = (lane < 16) ? __expf(m - gm) : 0.f;
        float ssc = (lane < 16) ? s_sum[lane] * fct : 0.f;
        #pragma unroll
        for (int o = 8; o; o >>= 1) ssc += __shfl_xor_sync(0xffffffffu, ssc, o);
        if (lane < 16) s_f[lane] = fct;
        if (lane == 0) s_red[0] = 1.f / ssc;
    }
    __syncthreads();
    const float inv = s_red[0];

    if (tid < DD) {
        float vb = 0.f;
        #pragma unroll
        for (int pI = 0; pI < 16; ++pI) vb += s_vpart[pI][tid] * s_f[pI];
        s_vec[tid] = vb * inv;
    }
    __syncthreads();

    // ---- out = W_value @ vbar ----
    if (tid < DD) {
        float s = 0.f;
        #pragma unroll
        for (int j = 0; j < DD; ++j) s += Wv[tid * DD + j] * s_vec[j];
        out[b * DD + tid] = s;
    }
}

extern "C" void kernel_launch(void* const* d_in, const int* in_sizes, int n_in,
                              void* d_out, int out_size) {
    const float* target_key  = (const float*)d_in[0];
    const float* item_keys   = (const float*)d_in[1];
    const float* item_values = (const float*)d_in[2];
    const int*   mask        = (const int*)  d_in[3];
    const float* W_target    = (const float*)d_in[4];
    const float* W_item      = (const float*)d_in[5];
    const float* W_value     = (const float*)d_in[6];
    float* out = (float*)d_out;

    precompute_M_kernel<<<DD, DD>>>(W_target, W_item);
    target_attn_kernel<<<BB, 256>>>(target_key, item_keys, item_values,
                                    mask, W_value, out);
}

// round 6
// speedup vs baseline: 2.8513x; 2.2862x over previous
#include <cuda_runtime.h>

#define BB 4096
#define LL 200
#define DD 64
#define NPAIR 100   // L/2 item pairs
#define NITER 13    // ceil(100/8)

// Transposed fused projection matrices (coalesced matvec access):
// g_MT[j][d]  = M^T  where M = W_item^T @ W_target  (qk = M @ tk)
// g_WvT[j][d] = Wv^T                                 (out = Wv @ vbar)
__device__ float g_MT [DD * DD];
__device__ float g_WvT[DD * DD];

// MT[dp][d] = M[d][dp] = sum_e W_item[e][d] * W_target[e][dp]
__global__ void precompute_kernel(const float* __restrict__ W_target,
                                  const float* __restrict__ W_item,
                                  const float* __restrict__ W_value) {
    int d  = blockIdx.x;    // 0..63
    int dp = threadIdx.x;   // 0..63
    float s = 0.f;
    #pragma unroll
    for (int e = 0; e < DD; ++e)
        s += W_item[e * DD + d] * W_target[e * DD + dp];
    g_MT[dp * DD + d] = s;                    // transposed store
    g_WvT[dp * DD + d] = W_value[d * DD + dp]; // Wv^T
}

__global__ __launch_bounds__(256, 4) void target_attn_kernel(
    const float* __restrict__ tk,    // [B, D]
    const float* __restrict__ ik,    // [B, L, D]
    const float* __restrict__ iv,    // [B, L, D]
    const int*   __restrict__ mask,  // [B, L]
    float* __restrict__ out)         // [B, D]
{
    const int b    = blockIdx.x;
    const int tid  = threadIdx.x;
    const int warp = tid >> 5;
    const int lane = tid & 31;
    const int half = lane >> 4;       // which item of the pair
    const int hl   = lane & 15;       // lane within half-warp
    const int st   = warp * 2 + half; // online-softmax state id (0..15)

    __shared__ __align__(16) float s_vec[DD];       // tk, later vbar
    __shared__ __align__(16) float s_qk[DD];        // fused query (pre-scaled)
    __shared__ __align__(16) float s_vpart[16][DD]; // per-state vbar partials
    __shared__ float s_bias[LL];                    // 0 or -1e8 per item
    __shared__ float s_mx[16];
    __shared__ float s_sum[16];
    __shared__ float s_f[16];
    __shared__ float s_red[2];

    // ---- coalesced preloads ----
    if (tid < LL) s_bias[tid] = mask[b * LL + tid] ? 0.f : -1e8f;
    if (tid < DD) s_vec[tid] = tk[b * DD + tid];
    __syncthreads();

    // ---- qk = (M @ tk) * (1/sqrt(D)); coalesced via M^T ----
    if (tid < DD) {
        float s = 0.f;
        #pragma unroll
        for (int j = 0; j < DD; ++j) s += g_MT[j * DD + tid] * s_vec[j];
        s_qk[tid] = s * 0.125f;
    }
    __syncthreads();

    // ---- fused streaming pass: 3-stage pipeline, 6 LDG.128 in flight/warp ----
    const float4 q4 = reinterpret_cast<const float4*>(s_qk)[hl];
    const float4* ik4 = reinterpret_cast<const float4*>(ik + (size_t)b * LL * DD);
    const float4* iv4 = reinterpret_cast<const float4*>(iv + (size_t)b * LL * DD);

    float mx  = -3.0e38f;
    float sum = 0.f;
    float4 acc = make_float4(0.f, 0.f, 0.f, 0.f);

    float4 A[3], V[3];
    {   // stages 0 and 1 always valid: warp+8 <= 15 < 100
        const int i0 = warp * 32 + lane;
        A[0] = ik4[i0];            V[0] = iv4[i0];
        const int i1 = i0 + 8 * 32;
        A[1] = ik4[i1];            V[1] = iv4[i1];
    }

    #pragma unroll
    for (int i = 0; i < NITER; ++i) {
        const int p  = warp + 8 * i;
        const int pf = warp + 8 * (i + 2);
        if (pf < NPAIR) {
            A[(i + 2) % 3] = ik4[pf * 32 + lane];
            V[(i + 2) % 3] = iv4[pf * 32 + lane];
        }
        if (p < NPAIR) {
            const float4 a = A[i % 3];
            const float4 v = V[i % 3];

            float s = a.x * q4.x + a.y * q4.y + a.z * q4.z + a.w * q4.w;
            s += __shfl_xor_sync(0xffffffffu, s, 8);
            s += __shfl_xor_sync(0xffffffffu, s, 4);
            s += __shfl_xor_sync(0xffffffffu, s, 2);
            s += __shfl_xor_sync(0xffffffffu, s, 1);
            s += s_bias[2 * p + half];

            const float nmx = fmaxf(mx, s);
            const float f   = __expf(mx - nmx);
            const float w   = __expf(s  - nmx);
            mx  = nmx;
            sum = sum * f + w;
            acc.x = acc.x * f + w * v.x;
            acc.y = acc.y * f + w * v.y;
            acc.z = acc.z * f + w * v.z;
            acc.w = acc.w * f + w * v.w;
        }
    }

    // ---- publish per-state results ----
    if (hl == 0) { s_mx[st] = mx; s_sum[st] = sum; }
    reinterpret_cast<float4*>(&s_vpart[st][hl * 4])[0] = acc;
    __syncthreads();

    // ---- merge 16 online-softmax states (warp 0) ----
    if (warp == 0) {
        float m = (lane < 16) ? s_mx[lane] : -3.0e38f;
        float gm = m;
        #pragma unroll
        for (int o = 8; o; o >>= 1) gm = fmaxf(gm, __shfl_xor_sync(0xffffffffu, gm, o));
        float fct = (lane < 16) ? __expf(m - gm) : 0.f;
        float ssc = (lane < 16) ? s_sum[lane] * fct : 0.f;
        #pragma unroll
        for (int o = 8; o; o >>= 1) ssc += __shfl_xor_sync(0xffffffffu, ssc, o);
        if (lane < 16) s_f[lane] = fct;
        if (lane == 0) s_red[0] = 1.f / ssc;
    }
    __syncthreads();
    const float inv = s_red[0];

    if (tid < DD) {
        float vb = 0.f;
        #pragma unroll
        for (int pI = 0; pI < 16; ++pI) vb += s_vpart[pI][tid] * s_f[pI];
        s_vec[tid] = vb * inv;
    }
    __syncthreads();

    // ---- out = Wv @ vbar; coalesced via Wv^T ----
    if (tid < DD) {
        float s = 0.f;
        #pragma unroll
        for (int j = 0; j < DD; ++j) s += g_WvT[j * DD + tid] * s_vec[j];
        out[b * DD + tid] = s;
    }
}

extern "C" void kernel_launch(void* const* d_in, const int* in_sizes, int n_in,
                              void* d_out, int out_size) {
    const float* target_key  = (const float*)d_in[0];
    const float* item_keys   = (const float*)d_in[1];
    const float* item_values = (const float*)d_in[2];
    const int*   mask        = (const int*)  d_in[3];
    const float* W_target    = (const float*)d_in[4];
    const float* W_item      = (const float*)d_in[5];
    const float* W_value     = (const float*)d_in[6];
    float* out = (float*)d_out;

    precompute_kernel<<<DD, DD>>>(W_target, W_item, W_value);
    target_attn_kernel<<<BB, 256>>>(target_key, item_keys, item_values,
                                    mask, out);
}

// round 7
// speedup vs baseline: 2.8525x; 1.0004x over previous
#include <cuda_runtime.h>

#define BB 4096
#define LL 200
#define DD 64
#define NPAIR 100   // L/2 item pairs
#define NITER 13    // ceil(100/8)
#define STAGES 4    // per-warp cp.async ring depth

// Transposed fused projection matrices (coalesced matvec access):
// g_MT[j][d]  = M^T  where M = W_item^T @ W_target  (qk = M @ tk)
// g_WvT[j][d] = Wv^T                                 (out = Wv @ vbar)
__device__ float g_MT [DD * DD];
__device__ float g_WvT[DD * DD];

__global__ void precompute_kernel(const float* __restrict__ W_target,
                                  const float* __restrict__ W_item,
                                  const float* __restrict__ W_value) {
    int d  = blockIdx.x;    // 0..63
    int dp = threadIdx.x;   // 0..63
    float s = 0.f;
    #pragma unroll
    for (int e = 0; e < DD; ++e)
        s += W_item[e * DD + d] * W_target[e * DD + dp];
    g_MT[dp * DD + d] = s;                     // M^T
    g_WvT[dp * DD + d] = W_value[d * DD + dp]; // Wv^T
}

__global__ __launch_bounds__(256, 5) void target_attn_kernel(
    const float* __restrict__ tk,    // [B, D]
    const float* __restrict__ ik,    // [B, L, D]
    const float* __restrict__ iv,    // [B, L, D]
    const int*   __restrict__ mask,  // [B, L]
    float* __restrict__ out)         // [B, D]
{
    const int b    = blockIdx.x;
    const int tid  = threadIdx.x;
    const int warp = tid >> 5;
    const int lane = tid & 31;
    const int half = lane >> 4;       // which item of the pair
    const int hl   = lane & 15;       // lane within half-warp
    const int st   = warp * 2 + half; // online-softmax state id (0..15)

    // per-warp pipeline: [warp][stage][ik 128 floats | iv 128 floats] = 1KB/stage
    __shared__ __align__(16) float s_pipe[8][STAGES][256];
    __shared__ __align__(16) float s_vec[DD];
    __shared__ __align__(16) float s_qk[DD];
    __shared__ __align__(16) float s_vpart[16][DD];
    __shared__ float s_bias[LL];
    __shared__ float s_mx[16];
    __shared__ float s_sum[16];
    __shared__ float s_f[16];
    __shared__ float s_red[2];

    // ---- coalesced preloads ----
    if (tid < LL) s_bias[tid] = mask[b * LL + tid] ? 0.f : -1e8f;
    if (tid < DD) s_vec[tid] = tk[b * DD + tid];

    // ---- start streaming pipeline immediately (no barrier needed: per-warp) ----
    const float* ikg = ik + (size_t)b * LL * DD;
    const float* ivg = iv + (size_t)b * LL * DD;
    const unsigned pipe_base =
        (unsigned)__cvta_generic_to_shared(&s_pipe[warp][0][0]);

    #pragma unroll
    for (int s = 0; s < STAGES; ++s) {   // pairs warp+8s <= 31 < 100: always valid
        const float* srcA = ikg + (warp + 8 * s) * 128 + lane * 4;
        const float* srcV = ivg + (warp + 8 * s) * 128 + lane * 4;
        unsigned d = pipe_base + s * 1024 + lane * 16;
        asm volatile(
            "cp.async.cg.shared.global [%0], [%1], 16;\n"
            "cp.async.cg.shared.global [%2], [%3], 16;\n"
            "cp.async.commit_group;\n"
            :: "r"(d), "l"(srcA), "r"(d + 512), "l"(srcV) : "memory");
    }

    __syncthreads();   // covers s_bias / s_vec

    // ---- qk = (M @ tk) * (1/sqrt(D)); coalesced via M^T ----
    if (tid < DD) {
        float s = 0.f;
        #pragma unroll
        for (int j = 0; j < DD; ++j) s += g_MT[j * DD + tid] * s_vec[j];
        s_qk[tid] = s * 0.125f;
    }
    __syncthreads();

    const float4 q4 = reinterpret_cast<const float4*>(s_qk)[hl];

    float mx  = -3.0e38f;
    float sum = 0.f;
    float4 acc = make_float4(0.f, 0.f, 0.f, 0.f);

    #pragma unroll
    for (int i = 0; i < NITER; ++i) {
        const int p = warp + 8 * i;
        if (p < NPAIR) {
            // wait until group i lands (<=3 groups pending)
            asm volatile("cp.async.wait_group 3;" ::: "memory");

            const int slot = i & 3;
            const float4 a = reinterpret_cast<const float4*>(
                                 &s_pipe[warp][slot][0])[lane];
            const float4 v = reinterpret_cast<const float4*>(
                                 &s_pipe[warp][slot][128])[lane];

            // prefetch group i+STAGES into the slot we just read (after read)
            const int pf = warp + 8 * (i + STAGES);
            if (pf < NPAIR) {
                const float* srcA = ikg + pf * 128 + lane * 4;
                const float* srcV = ivg + pf * 128 + lane * 4;
                unsigned d = pipe_base + slot * 1024 + lane * 16;
                asm volatile(
                    "cp.async.cg.shared.global [%0], [%1], 16;\n"
                    "cp.async.cg.shared.global [%2], [%3], 16;\n"
                    :: "r"(d), "l"(srcA), "r"(d + 512), "l"(srcV) : "memory");
            }
            // exactly one commit per iteration keeps wait_group cadence exact
            asm volatile("cp.async.commit_group;" ::: "memory");

            float s = a.x * q4.x + a.y * q4.y + a.z * q4.z + a.w * q4.w;
            s += __shfl_xor_sync(0xffffffffu, s, 8);
            s += __shfl_xor_sync(0xffffffffu, s, 4);
            s += __shfl_xor_sync(0xffffffffu, s, 2);
            s += __shfl_xor_sync(0xffffffffu, s, 1);
            s += s_bias[2 * p + half];

            const float nmx = fmaxf(mx, s);
            const float f   = __expf(mx - nmx);
            const float w   = __expf(s  - nmx);
            mx  = nmx;
            sum = sum * f + w;
            acc.x = acc.x * f + w * v.x;
            acc.y = acc.y * f + w * v.y;
            acc.z = acc.z * f + w * v.z;
            acc.w = acc.w * f + w * v.w;
        }
    }

    // ---- publish per-state results ----
    if (hl == 0) { s_mx[st] = mx; s_sum[st] = sum; }
    reinterpret_cast<float4*>(&s_vpart[st][hl * 4])[0] = acc;
    __syncthreads();

    // ---- merge 16 online-softmax states (warp 0) ----
    if (warp == 0) {
        float m = (lane < 16) ? s_mx[lane] : -3.0e38f;
        float gm = m;
        #pragma unroll
        for (int o = 8; o; o >>= 1) gm = fmaxf(gm, __shfl_xor_sync(0xffffffffu, gm, o));
        float fct = (lane < 16) ? __expf(m - gm) : 0.f;
        float ssc = (lane < 16) ? s_sum[lane] * fct : 0.f;
        #pragma unroll
        for (int o = 8; o; o >>= 1) ssc += __shfl_xor_sync(0xffffffffu, ssc, o);
        if (lane < 16) s_f[lane] = fct;
        if (lane == 0) s_red[0] = 1.f / ssc;
    }
    __syncthreads();
    const float inv = s_red[0];

    if (tid < DD) {
        float vb = 0.f;
        #pragma unroll
        for (int pI = 0; pI < 16; ++pI) vb += s_vpart[pI][tid] * s_f[pI];
        s_vec[tid] = vb * inv;
    }
    __syncthreads();

    // ---- out = Wv @ vbar; coalesced via Wv^T ----
    if (tid < DD) {
        float s = 0.f;
        #pragma unroll
        for (int j = 0; j < DD; ++j) s += g_WvT[j * DD + tid] * s_vec[j];
        out[b * DD + tid] = s;
    }
}

extern "C" void kernel_launch(void* const* d_in, const int* in_sizes, int n_in,
                              void* d_out, int out_size) {
    const float* target_key  = (const float*)d_in[0];
    const float* item_keys   = (const float*)d_in[1];
    const float* item_values = (const float*)d_in[2];
    const int*   mask        = (const int*)  d_in[3];
    const float* W_target    = (const float*)d_in[4];
    const float* W_item      = (const float*)d_in[5];
    const float* W_value     = (const float*)d_in[6];
    float* out = (float*)d_out;

    precompute_kernel<<<DD, DD>>>(W_target, W_item, W_value);
    target_attn_kernel<<<BB, 256>>>(target_key, item_keys, item_values,
                                    mask, out);
}

// round 8
// speedup vs baseline: 4.0733x; 1.4280x over previous
#include <cuda_runtime.h>

#define BB 4096
#define LL 200
#define DD 64
#define STAGES 4    // per-warp cp.async ring depth

// Transposed fused projection matrices (coalesced matvec access):
// g_MT[j][d]  = M^T  where M = W_item^T @ W_target  (qk = M @ tk)
// g_WvT[j][d] = Wv^T                                 (out = Wv @ vbar)
__device__ float g_MT [DD * DD];
__device__ float g_WvT[DD * DD];

__global__ void precompute_kernel(const float* __restrict__ W_target,
                                  const float* __restrict__ W_item,
                                  const float* __restrict__ W_value) {
    int d  = blockIdx.x;    // 0..63
    int dp = threadIdx.x;   // 0..63
    float s = 0.f;
    #pragma unroll
    for (int e = 0; e < DD; ++e)
        s += W_item[e * DD + d] * W_target[e * DD + dp];
    g_MT[dp * DD + d] = s;                     // M^T
    g_WvT[dp * DD + d] = W_value[d * DD + dp]; // Wv^T
}

__global__ __launch_bounds__(256, 5) void target_attn_kernel(
    const float* __restrict__ tk,    // [B, D]
    const float* __restrict__ ik,    // [B, L, D]
    const float* __restrict__ iv,    // [B, L, D]
    const int*   __restrict__ mask,  // [B, L]
    float* __restrict__ out)         // [B, D]
{
    const int b    = blockIdx.x;
    const int tid  = threadIdx.x;
    const int warp = tid >> 5;
    const int lane = tid & 31;
    const int half = lane >> 4;       // which item of the pair
    const int hl   = lane & 15;       // lane within half-warp
    const int st   = warp * 2 + half; // online-softmax state id (0..15)

    // per-warp pipeline: [warp][stage][ik 128 floats | iv 128 floats] = 1KB/stage
    __shared__ __align__(16) float s_pipe[8][STAGES][256];
    __shared__ __align__(16) float s_vec[DD];
    __shared__ __align__(16) float s_qk[DD];
    __shared__ __align__(16) float s_vpart[16][DD];
    __shared__ int   s_mask[LL];
    __shared__ int   s_idx[LL + 1];   // compacted active indices + sentinel
    __shared__ int   s_nact;
    __shared__ float s_mx[16];
    __shared__ float s_sum[16];
    __shared__ float s_f[16];
    __shared__ float s_red[2];

    // ---- coalesced preloads ----
    if (tid < LL) s_mask[tid] = mask[b * LL + tid];
    if (tid < DD) s_vec[tid] = tk[b * DD + tid];
    __syncthreads();

    // ---- warp 0: ballot compaction of active indices ----
    if (warp == 0) {
        int base = 0;
        #pragma unroll
        for (int c = 0; c < 7; ++c) {
            const int l = c * 32 + lane;
            const bool act = (l < LL) && (s_mask[l] != 0);
            const unsigned bal = __ballot_sync(0xffffffffu, act);
            const int pos = base + __popc(bal & ((1u << lane) - 1u));
            if (act) s_idx[pos] = l;
            base += __popc(bal);
        }
        if (base == 0) {
            // all-masked fallback: softmax(s-1e8)=softmax(s) -> all items active
            #pragma unroll
            for (int c = 0; c < 7; ++c) {
                const int l = c * 32 + lane;
                if (l < LL) s_idx[l] = l;
            }
            base = LL;
        }
        if (lane == 0) {
            s_idx[base] = s_idx[0];   // sentinel for odd tail (safe addr)
            s_nact = base;
        }
    }

    // ---- warps 2,3: qk = (M @ tk) * (1/sqrt(D)) concurrently ----
    if (tid >= 64 && tid < 128) {
        const int d = tid - 64;
        float s = 0.f;
        #pragma unroll
        for (int j = 0; j < DD; ++j) s += g_MT[j * DD + d] * s_vec[j];
        s_qk[d] = s * 0.125f;
    }
    __syncthreads();

    const int   n_act = s_nact;
    const int   npair = (n_act + 1) >> 1;
    const float4 q4 = reinterpret_cast<const float4*>(s_qk)[hl];
    const float* ikg = ik + (size_t)b * LL * DD;
    const float* ivg = iv + (size_t)b * LL * DD;
    const unsigned pipe_base =
        (unsigned)__cvta_generic_to_shared(&s_pipe[warp][0][0]);

    // ---- prologue: fill ring (always commit to keep cadence) ----
    #pragma unroll
    for (int s = 0; s < STAGES; ++s) {
        const int p = warp + 8 * s;
        if (p < npair) {
            const int idx = s_idx[2 * p + half];    // 16-lane broadcast
            const float* srcA = ikg + (size_t)idx * DD + hl * 4;
            const float* srcV = ivg + (size_t)idx * DD + hl * 4;
            unsigned d = pipe_base + s * 1024 + lane * 16;
            asm volatile(
                "cp.async.cg.shared.global [%0], [%1], 16;\n"
                "cp.async.cg.shared.global [%2], [%3], 16;\n"
                :: "r"(d), "l"(srcA), "r"(d + 512), "l"(srcV) : "memory");
        }
        asm volatile("cp.async.commit_group;" ::: "memory");
    }

    float mx  = -3.0e38f;
    float sum = 0.f;
    float4 acc = make_float4(0.f, 0.f, 0.f, 0.f);

    for (int i = 0; ; ++i) {
        const int p = warp + 8 * i;
        if (p >= npair) break;

        asm volatile("cp.async.wait_group 3;" ::: "memory");

        const int slot = i & 3;
        const float4 a = reinterpret_cast<const float4*>(
                             &s_pipe[warp][slot][0])[lane];
        const float4 v = reinterpret_cast<const float4*>(
                             &s_pipe[warp][slot][128])[lane];

        // prefetch pair p+8*STAGES into the slot just consumed
        const int pf = warp + 8 * (i + STAGES);
        if (pf < npair) {
            const int idx = s_idx[2 * pf + half];
            const float* srcA = ikg + (size_t)idx * DD + hl * 4;
            const float* srcV = ivg + (size_t)idx * DD + hl * 4;
            unsigned d = pipe_base + slot * 1024 + lane * 16;
            asm volatile(
                "cp.async.cg.shared.global [%0], [%1], 16;\n"
                "cp.async.cg.shared.global [%2], [%3], 16;\n"
                :: "r"(d), "l"(srcA), "r"(d + 512), "l"(srcV) : "memory");
        }
        asm volatile("cp.async.commit_group;" ::: "memory");

        float s = a.x * q4.x + a.y * q4.y + a.z * q4.z + a.w * q4.w;
        s += __shfl_xor_sync(0xffffffffu, s, 8);
        s += __shfl_xor_sync(0xffffffffu, s, 4);
        s += __shfl_xor_sync(0xffffffffu, s, 2);
        s += __shfl_xor_sync(0xffffffffu, s, 1);
        if (2 * p + half >= n_act) s = -1e8f;   // odd-tail sentinel: weight 0

        const float nmx = fmaxf(mx, s);
        const float f   = __expf(mx - nmx);
        const float w   = __expf(s  - nmx);
        mx  = nmx;
        sum = sum * f + w;
        acc.x = acc.x * f + w * v.x;
        acc.y = acc.y * f + w * v.y;
        acc.z = acc.z * f + w * v.z;
        acc.w = acc.w * f + w * v.w;
    }

    // ---- publish per-state results ----
    if (hl == 0) { s_mx[st] = mx; s_sum[st] = sum; }
    reinterpret_cast<float4*>(&s_vpart[st][hl * 4])[0] = acc;
    __syncthreads();

    // ---- merge 16 online-softmax states (warp 0) ----
    if (warp == 0) {
        float m = (lane < 16) ? s_mx[lane] : -3.0e38f;
        float gm = m;
        #pragma unroll
        for (int o = 8; o; o >>= 1) gm = fmaxf(gm, __shfl_xor_sync(0xffffffffu, gm, o));
        float fct = (lane < 16) ? __expf(m - gm) : 0.f;
        float ssc = (lane < 16) ? s_sum[lane] * fct : 0.f;
        #pragma unroll
        for (int o = 8; o; o >>= 1) ssc += __shfl_xor_sync(0xffffffffu, ssc, o);
        if (lane < 16) s_f[lane] = fct;
        if (lane == 0) s_red[0] = 1.f / ssc;
    }
    __syncthreads();
    const float inv = s_red[0];

    if (tid < DD) {
        float vb = 0.f;
        #pragma unroll
        for (int pI = 0; pI < 16; ++pI) vb += s_vpart[pI][tid] * s_f[pI];
        s_vec[tid] = vb * inv;
    }
    __syncthreads();

    // ---- out = Wv @ vbar; coalesced via Wv^T ----
    if (tid < DD) {
        float s = 0.f;
        #pragma unroll
        for (int j = 0; j < DD; ++j) s += g_WvT[j * DD + tid] * s_vec[j];
        out[b * DD + tid] = s;
    }
}

extern "C" void kernel_launch(void* const* d_in, const int* in_sizes, int n_in,
                              void* d_out, int out_size) {
    const float* target_key  = (const float*)d_in[0];
    const float* item_keys   = (const float*)d_in[1];
    const float* item_values = (const float*)d_in[2];
    const int*   mask        = (const int*)  d_in[3];
    const float* W_target    = (const float*)d_in[4];
    const float* W_item      = (const float*)d_in[5];
    const float* W_value     = (const float*)d_in[6];
    float* out = (float*)d_out;

    precompute_kernel<<<DD, DD>>>(W_target, W_item, W_value);
    target_attn_kernel<<<BB, 256>>>(target_key, item_keys, item_values,
                                    mask, out);
}